// round 11
// baseline (speedup 1.0000x reference)
#include <cuda_runtime.h>

#define BB 64
#define NN 256
#define EE 2048
#define DD 128
#define PD 132          // padded smem pitch (floats)
#define HH 4
#define LCAP 64
#define XCAP 32
#define NPROD 16
#define NEG_SLOPE 0.2f

// Folded weight partials (16 producer blocks; consumers sum the two halves)
__device__ float g_wsp[2][2 * HH * DD];
__device__ float g_wdp[2][2 * HH * DD];
__device__ float g_up [2][2 * HH * DD];
__device__ float g_const;
__device__ int   g_done = 0;   // producers arrived (0..16)
__device__ int   g_pass = 0;   // consumer blocks past the wait (0..64); last resets

__global__ __launch_bounds__(256)
void gat_fused(const float* __restrict__ W1, const float* __restrict__ as1,
               const float* __restrict__ ad1,
               const float* __restrict__ W2, const float* __restrict__ as2,
               const float* __restrict__ ad2,
               const float* __restrict__ mlp_w, const float* __restrict__ mlp_b,
               const float* __restrict__ b1, const float* __restrict__ b2,
               const int* __restrict__ adj1, const int* __restrict__ adj2,
               const int* __restrict__ nbr1, const int* __restrict__ nbr2,
               const float* __restrict__ emb, float* __restrict__ out) {
    const int tid = threadIdx.x;

    // ───────── Producer blocks: fold weights (16 blocks) ─────────
    if (blockIdx.x < NPROD) {
        __shared__ float r0[128], r1[128], r2[128];
        const int bx = blockIdx.x;
        const int br = bx >> 3, h = (bx >> 1) & 3, half = bx & 1;
        const float* W   = br ? W2  : W1;
        const float* as_ = br ? as2 : as1;
        const float* ad_ = br ? ad2 : ad1;
        const float* mw  = mlp_w + br * DD;
        const int k = tid & 127, p = tid >> 7;

        float aws = 0.f, awd = 0.f, au = 0.f;
        #pragma unroll
        for (int dd = 0; dd < 32; ++dd) {
            int d = half * 64 + p * 32 + dd;
            float wv = W[(h * DD + d) * DD + k];
            aws += wv * as_[h * DD + d];
            awd += wv * ad_[h * DD + d];
            au  += wv * mw[d];
        }
        if (p == 1) { r0[k] = aws; r1[k] = awd; r2[k] = au; }
        __syncthreads();
        if (p == 0) {
            const int idx = (br * HH + h) * DD + k;
            g_wsp[half][idx] = aws + r0[k];
            g_wdp[half][idx] = awd + r1[k];
            g_up [half][idx] = au  + r2[k];
        }
        if (bx == 0 && tid >= 128 && tid < 160) {
            int l = tid - 128;
            float c = 0.f;
            for (int d = l; d < DD; d += 32)
                c += mlp_w[d] * b1[d] + mlp_w[DD + d] * b2[d];
            #pragma unroll
            for (int o = 16; o; o >>= 1) c += __shfl_xor_sync(0xffffffffu, c, o);
            if (l == 0) g_const = c + mlp_b[0];
        }
        __syncthreads();
        if (tid == 0) { __threadfence(); atomicAdd(&g_done, 1); }
        return;
    }

    // ───────── Consumer blocks: one batch each ─────────
    __shared__ float sws[2][HH][PD], swd[2][HH][PD], su[2][HH][PD];
    __shared__ float s_x[2][XCAP + 1][PD];   // row XCAP = center node
    __shared__ int   s_nbr[2][NN];
    __shared__ int   s_list[2][LCAP];        // arrival order: e<<15 | slot<<8 | src
    __shared__ int   s_sorted[2][LCAP + 1];  // edge order + self-loop last
    __shared__ int   s_cnt[2], s_n[2];
    __shared__ float s_e[2][LCAP + 1][HH];   // raw src dots per slot (LCAP = center)
    __shared__ float s_p[2][LCAP + 1][HH];
    __shared__ float s_adst[2][HH];

    const int b = blockIdx.x - NPROD;
    const int warp = tid >> 5, lane = tid & 31;
    const float NEGINF = __int_as_float(0xff800000);

    if (tid < 2) s_cnt[tid] = 0;
    __syncthreads();

    // Stage nbr rows (independent — overlaps scan loads)
    s_nbr[0][tid] = nbr1[b * NN + tid];
    s_nbr[1][tid] = nbr2[b * NN + tid];

    // Parallel scan: 128 threads per branch, 16 edges each
    {
        const int brx = tid >> 7, t = tid & 127;
        const int e0 = t * 16;
        const int* base = (brx ? adj2 : adj1) + (long)b * 2 * EE;
        int4 vd[4], vs[4];
        #pragma unroll
        for (int q = 0; q < 4; ++q) {
            vd[q] = *(const int4*)(base + EE + e0 + 4 * q);
            vs[q] = *(const int4*)(base +      e0 + 4 * q);
        }
        #pragma unroll
        for (int q = 0; q < 4; ++q) {
            int d4[4] = { vd[q].x, vd[q].y, vd[q].z, vd[q].w };
            int s4[4] = { vs[q].x, vs[q].y, vs[q].z, vs[q].w };
            #pragma unroll
            for (int i = 0; i < 4; ++i) {
                if (d4[i] == 0) {
                    int slot = atomicAdd(&s_cnt[brx], 1);
                    if (slot < LCAP)
                        s_list[brx][slot] = ((e0 + 4 * q + i) << 15) | (slot << 8) | s4[i];
                }
            }
        }
    }
    __syncthreads();

    // Overlap phase:
    //   Warps 1-7 (14 half-warp groups): gather emb rows (slot order).
    //   Warp 0: sort into s_sorted (lanes 0/16), poll for producers (lane 0),
    //           then stage ALL folded weights itself (overlaps the gather round).
    if (warp > 0) {
        const int c0 = min(min(s_cnt[0], LCAP), XCAP) + 1;   // +1 = center row
        const int c1 = min(min(s_cnt[1], LCAP), XCAP) + 1;
        const int hw = (warp - 1) * 2 + (lane >> 4);         // 0..13 half-warp id
        const int hl = lane & 15;                            // 0..15 within half-warp
        for (int i = hw; i < c0 + c1; i += 14) {
            const int brx = (i >= c0) ? 1 : 0;
            const int li  = brx ? (i - c0) : i;
            const int cc  = brx ? c1 : c0;
            int row, src;
            if (li == cc - 1) { row = XCAP; src = 0; }
            else             { row = li;   src = s_list[brx][li] & 255; }
            const float4 v0 = *(const float4*)(emb + (long)s_nbr[brx][src] * DD + hl * 8);
            const float4 v1 = *(const float4*)(emb + (long)s_nbr[brx][src] * DD + hl * 8 + 4);
            *(float4*)&s_x[brx][row][hl * 8]     = v0;
            *(float4*)&s_x[brx][row][hl * 8 + 4] = v1;
        }
    } else {
        if (lane == 0 || lane == 16) {
            const int brx = lane >> 4;
            const int n = min(s_cnt[brx], LCAP);
            for (int i = 0; i < n; ++i) {
                int key = s_list[brx][i], j = i - 1;
                while (j >= 0 && s_sorted[brx][j] > key) { s_sorted[brx][j + 1] = s_sorted[brx][j]; --j; }
                s_sorted[brx][j + 1] = key;
            }
            s_sorted[brx][n] = (EE << 15) | (LCAP << 8);   // self-loop -> center slot
            s_n[brx] = n;
        }
        if (lane == 0) {
            const volatile int* pd = &g_done;
            while (*pd < NPROD) {}
            __threadfence();
            int fin = atomicAdd(&g_pass, 1);
            if (fin == BB - 1) { g_done = 0; g_pass = 0; __threadfence(); }
        }
        __syncwarp();
        // Warp 0 stages all folded weights: 8 float4 per lane per array
        {
            const float4* a0 = (const float4*)g_wsp[0];
            const float4* a1 = (const float4*)g_wsp[1];
            const float4* b0 = (const float4*)g_wdp[0];
            const float4* b1_ = (const float4*)g_wdp[1];
            const float4* c0 = (const float4*)g_up[0];
            const float4* c1 = (const float4*)g_up[1];
            #pragma unroll
            for (int q = 0; q < 8; ++q) {
                const int idx = lane * 8 + q;         // 0..255
                const int rowi = idx >> 5, ki = (idx & 31) * 4;
                float4 va = a0[idx], vb = a1[idx];
                *(float4*)(&sws[0][0][0] + rowi * PD + ki) =
                    make_float4(va.x + vb.x, va.y + vb.y, va.z + vb.z, va.w + vb.w);
                va = b0[idx]; vb = b1_[idx];
                *(float4*)(&swd[0][0][0] + rowi * PD + ki) =
                    make_float4(va.x + vb.x, va.y + vb.y, va.z + vb.z, va.w + vb.w);
                va = c0[idx]; vb = c1[idx];
                *(float4*)(&su[0][0][0] + rowi * PD + ki) =
                    make_float4(va.x + vb.x, va.y + vb.y, va.z + vb.z, va.w + vb.w);
            }
        }
    }
    __syncthreads();   // gathers + sort + weight staging all complete

    // One-pass group compute: 8-lane groups; 16 groups per branch cover all jobs.
    // Jobs 0..n-1: source slots; job n: center src dot; job n+1: adst (swd).
    // Shuffles use the GROUP's 8-lane mask (trip counts differ between groups).
    {
        const int br  = warp >> 2;
        const int gl  = (warp & 3) * 4 + (lane >> 3);   // 0..15 within branch
        const int sub = lane & 7;
        const int d0  = sub * 16;
        const int n   = s_n[br];
        const unsigned gmask = 0xFFu << ((lane >> 3) * 8);

        for (int j = gl; j < n + 2; j += 16) {
            const bool isAdst   = (j == n + 1);
            const bool isCenter = (j >= n);
            const float* A = isAdst ? &swd[br][0][0] : &sws[br][0][0];
            const float* P = &su[br][0][0];
            float a0 = 0, a1 = 0, a2 = 0, a3 = 0, p0 = 0, p1 = 0, p2 = 0, p3 = 0;

            if (isCenter || j < XCAP) {
                const float* x = &s_x[br][isCenter ? XCAP : j][0];
                #pragma unroll
                for (int q = 0; q < 16; ++q) {
                    float xv = x[d0 + q];
                    a0 += xv * A[0 * PD + d0 + q]; a1 += xv * A[1 * PD + d0 + q];
                    a2 += xv * A[2 * PD + d0 + q]; a3 += xv * A[3 * PD + d0 + q];
                    p0 += xv * P[0 * PD + d0 + q]; p1 += xv * P[1 * PD + d0 + q];
                    p2 += xv * P[2 * PD + d0 + q]; p3 += xv * P[3 * PD + d0 + q];
                }
            } else {   // rare: slot beyond prefetch capacity
                const float* xg = emb + (long)s_nbr[br][s_list[br][j] & 255] * DD + d0;
                #pragma unroll
                for (int q = 0; q < 16; ++q) {
                    float xv = xg[q];
                    a0 += xv * A[0 * PD + d0 + q]; a1 += xv * A[1 * PD + d0 + q];
                    a2 += xv * A[2 * PD + d0 + q]; a3 += xv * A[3 * PD + d0 + q];
                    p0 += xv * P[0 * PD + d0 + q]; p1 += xv * P[1 * PD + d0 + q];
                    p2 += xv * P[2 * PD + d0 + q]; p3 += xv * P[3 * PD + d0 + q];
                }
            }
            #pragma unroll
            for (int o = 1; o <= 4; o <<= 1) {
                a0 += __shfl_xor_sync(gmask, a0, o);
                a1 += __shfl_xor_sync(gmask, a1, o);
                a2 += __shfl_xor_sync(gmask, a2, o);
                a3 += __shfl_xor_sync(gmask, a3, o);
                p0 += __shfl_xor_sync(gmask, p0, o);
                p1 += __shfl_xor_sync(gmask, p1, o);
                p2 += __shfl_xor_sync(gmask, p2, o);
                p3 += __shfl_xor_sync(gmask, p3, o);
            }
            if (sub == 0) {
                if (isAdst) {
                    s_adst[br][0] = a0; s_adst[br][1] = a1;
                    s_adst[br][2] = a2; s_adst[br][3] = a3;
                } else {
                    const int idx = isCenter ? LCAP : j;
                    s_e[br][idx][0] = a0; s_e[br][idx][1] = a1;
                    s_e[br][idx][2] = a2; s_e[br][idx][3] = a3;
                    s_p[br][idx][0] = p0; s_p[br][idx][1] = p1;
                    s_p[br][idx][2] = p2; s_p[br][idx][3] = p3;
                }
            }
        }
    }
    __syncthreads();

    // Final: 8 lanes, one (branch, head) each; sorted order -> deterministic
    if (warp == 0) {
        float val = 0.f;
        if (lane < 8) {
            const int brx = lane >> 2, h = lane & 3;
            const int n = s_n[brx];
            const float ad = s_adst[brx][h];
            float M = NEGINF;
            for (int i = 0; i <= n; ++i) {
                int row = (s_sorted[brx][i] >> 8) & 127;
                float e = s_e[brx][row][h] + ad;
                e = e > 0.f ? e : NEG_SLOPE * e;
                M = fmaxf(M, e);
            }
            float S = 0.f, T = 0.f;
            for (int i = 0; i <= n; ++i) {
                int row = (s_sorted[brx][i] >> 8) & 127;
                float e = s_e[brx][row][h] + ad;
                e = e > 0.f ? e : NEG_SLOPE * e;
                float w = __expf(e - M);
                S += w;
                T += w * s_p[brx][row][h];
            }
            val = __fdividef(T, S) * (1.f / HH);
        }
        #pragma unroll
        for (int o = 4; o; o >>= 1) val += __shfl_xor_sync(0xffffffffu, val, o);
        if (lane == 0) out[b] = val + g_const;
    }
}

extern "C" void kernel_launch(void* const* d_in, const int* in_sizes, int n_in,
                              void* d_out, int out_size) {
    const int*   nbr1 = (const int*)  d_in[0];
    const int*   nbr2 = (const int*)  d_in[1];
    const int*   adj1 = (const int*)  d_in[2];
    const int*   adj2 = (const int*)  d_in[3];
    const float* emb  = (const float*)d_in[4];
    const float* W1   = (const float*)d_in[5];
    const float* as1  = (const float*)d_in[6];
    const float* ad1  = (const float*)d_in[7];
    const float* b1   = (const float*)d_in[8];
    const float* W2   = (const float*)d_in[9];
    const float* as2  = (const float*)d_in[10];
    const float* ad2  = (const float*)d_in[11];
    const float* b2   = (const float*)d_in[12];
    const float* mw   = (const float*)d_in[13];
    const float* mb   = (const float*)d_in[14];
    float* out = (float*)d_out;

    gat_fused<<<NPROD + BB, 256>>>(W1, as1, ad1, W2, as2, ad2, mw, mb, b1, b2,
                                   adj1, adj2, nbr1, nbr2, emb, out);
}

// round 12
// speedup vs baseline: 1.0853x; 1.0853x over previous
#include <cuda_runtime.h>

#define BB 64
#define NN 256
#define EE 2048
#define DD 128
#define PD 132          // padded smem pitch (floats)
#define HH 4
#define LCAP 64
#define XCAP 32
#define NPROD 16
#define NEG_SLOPE 0.2f

// Folded weight partials (16 producer blocks; consumers sum the two halves)
__device__ float g_wsp[2][2 * HH * DD];
__device__ float g_wdp[2][2 * HH * DD];
__device__ float g_up [2][2 * HH * DD];
__device__ float g_const;
__device__ int   g_done = 0;   // producers arrived (0..16)
__device__ int   g_pass = 0;   // consumer blocks past the wait (0..64); last resets

__global__ __launch_bounds__(256)
void gat_fused(const float* __restrict__ W1, const float* __restrict__ as1,
               const float* __restrict__ ad1,
               const float* __restrict__ W2, const float* __restrict__ as2,
               const float* __restrict__ ad2,
               const float* __restrict__ mlp_w, const float* __restrict__ mlp_b,
               const float* __restrict__ b1, const float* __restrict__ b2,
               const int* __restrict__ adj1, const int* __restrict__ adj2,
               const int* __restrict__ nbr1, const int* __restrict__ nbr2,
               const float* __restrict__ emb, float* __restrict__ out) {
    const int tid = threadIdx.x;

    // ───────── Producer blocks: fold weights (16 blocks) ─────────
    if (blockIdx.x < NPROD) {
        __shared__ float r0[128], r1[128], r2[128];
        const int bx = blockIdx.x;
        const int br = bx >> 3, h = (bx >> 1) & 3, half = bx & 1;
        const float* W   = br ? W2  : W1;
        const float* as_ = br ? as2 : as1;
        const float* ad_ = br ? ad2 : ad1;
        const float* mw  = mlp_w + br * DD;
        const int k = tid & 127, p = tid >> 7;

        float aws = 0.f, awd = 0.f, au = 0.f;
        #pragma unroll
        for (int dd = 0; dd < 32; ++dd) {
            int d = half * 64 + p * 32 + dd;
            float wv = W[(h * DD + d) * DD + k];
            aws += wv * as_[h * DD + d];
            awd += wv * ad_[h * DD + d];
            au  += wv * mw[d];
        }
        if (p == 1) { r0[k] = aws; r1[k] = awd; r2[k] = au; }
        __syncthreads();
        if (p == 0) {
            const int idx = (br * HH + h) * DD + k;
            g_wsp[half][idx] = aws + r0[k];
            g_wdp[half][idx] = awd + r1[k];
            g_up [half][idx] = au  + r2[k];
        }
        if (bx == 0 && tid >= 128 && tid < 160) {
            int l = tid - 128;
            float c = 0.f;
            for (int d = l; d < DD; d += 32)
                c += mlp_w[d] * b1[d] + mlp_w[DD + d] * b2[d];
            #pragma unroll
            for (int o = 16; o; o >>= 1) c += __shfl_xor_sync(0xffffffffu, c, o);
            if (l == 0) g_const = c + mlp_b[0];
        }
        __syncthreads();
        if (tid == 0) { __threadfence(); atomicAdd(&g_done, 1); }
        return;
    }

    // ───────── Consumer blocks: one batch each ─────────
    __shared__ float sws[2][HH][PD], swd[2][HH][PD], su[2][HH][PD];
    __shared__ float s_x[2][XCAP + 1][PD];   // row XCAP = center node
    __shared__ int   s_nbr[2][NN];
    __shared__ int   s_list[2][LCAP];        // arrival order: e<<15 | slot<<8 | src
    __shared__ int   s_sorted[2][LCAP + 1];  // edge order + self-loop last
    __shared__ int   s_cnt[2], s_n[2];
    __shared__ float s_e[2][LCAP + 1][HH];   // raw src dots per slot (LCAP = center)
    __shared__ float s_p[2][LCAP + 1][HH];
    __shared__ float s_adst[2][HH];

    const int b = blockIdx.x - NPROD;
    const int warp = tid >> 5, lane = tid & 31;
    const float NEGINF = __int_as_float(0xff800000);

    if (tid < 2) s_cnt[tid] = 0;
    __syncthreads();

    // Stage nbr rows (independent — overlaps scan loads)
    s_nbr[0][tid] = nbr1[b * NN + tid];
    s_nbr[1][tid] = nbr2[b * NN + tid];

    // Parallel scan: 128 threads per branch, 16 edges each
    {
        const int brx = tid >> 7, t = tid & 127;
        const int e0 = t * 16;
        const int* base = (brx ? adj2 : adj1) + (long)b * 2 * EE;
        int4 vd[4], vs[4];
        #pragma unroll
        for (int q = 0; q < 4; ++q) {
            vd[q] = *(const int4*)(base + EE + e0 + 4 * q);
            vs[q] = *(const int4*)(base +      e0 + 4 * q);
        }
        #pragma unroll
        for (int q = 0; q < 4; ++q) {
            int d4[4] = { vd[q].x, vd[q].y, vd[q].z, vd[q].w };
            int s4[4] = { vs[q].x, vs[q].y, vs[q].z, vs[q].w };
            #pragma unroll
            for (int i = 0; i < 4; ++i) {
                if (d4[i] == 0) {
                    int slot = atomicAdd(&s_cnt[brx], 1);
                    if (slot < LCAP)
                        s_list[brx][slot] = ((e0 + 4 * q + i) << 15) | (slot << 8) | s4[i];
                }
            }
        }
    }
    __syncthreads();

    // Overlap phase:
    //   Warps 1-7 (14 half-warp groups): gather emb rows (slot order, ≤2 rounds).
    //   Warp 0: sort into s_sorted (lanes 0/16); lane 0 polls for producers.
    if (warp > 0) {
        const int c0 = min(min(s_cnt[0], LCAP), XCAP) + 1;   // +1 = center row
        const int c1 = min(min(s_cnt[1], LCAP), XCAP) + 1;
        const int hw = (warp - 1) * 2 + (lane >> 4);         // 0..13 half-warp id
        const int hl = lane & 15;                            // 0..15 within half-warp
        for (int i = hw; i < c0 + c1; i += 14) {
            const int brx = (i >= c0) ? 1 : 0;
            const int li  = brx ? (i - c0) : i;
            const int cc  = brx ? c1 : c0;
            int row, src;
            if (li == cc - 1) { row = XCAP; src = 0; }
            else             { row = li;   src = s_list[brx][li] & 255; }
            const float* xr = emb + (long)s_nbr[brx][src] * DD;
            const float4 v0 = *(const float4*)(xr + hl * 8);
            const float4 v1 = *(const float4*)(xr + hl * 8 + 4);
            *(float4*)&s_x[brx][row][hl * 8]     = v0;
            *(float4*)&s_x[brx][row][hl * 8 + 4] = v1;
        }
    } else {
        if (lane == 0 || lane == 16) {
            const int brx = lane >> 4;
            const int n = min(s_cnt[brx], LCAP);
            for (int i = 0; i < n; ++i) {
                int key = s_list[brx][i], j = i - 1;
                while (j >= 0 && s_sorted[brx][j] > key) { s_sorted[brx][j + 1] = s_sorted[brx][j]; --j; }
                s_sorted[brx][j + 1] = key;
            }
            s_sorted[brx][n] = (EE << 15) | (LCAP << 8);   // self-loop -> center slot
            s_n[brx] = n;
        }
        if (lane == 0) {
            const volatile int* pd = &g_done;
            while (*pd < NPROD) {}
            __threadfence();
            int fin = atomicAdd(&g_pass, 1);
            if (fin == BB - 1) { g_done = 0; g_pass = 0; __threadfence(); }
        }
    }
    __syncthreads();   // weights ready + gathers + sort all complete

    // Stage folded weights block-wide: one float4 per thread per array (one L2 round)
    {
        const float4* a0 = (const float4*)g_wsp[0];
        const float4* a1 = (const float4*)g_wsp[1];
        const float4* b0 = (const float4*)g_wdp[0];
        const float4* b1_ = (const float4*)g_wdp[1];
        const float4* c0 = (const float4*)g_up[0];
        const float4* c1 = (const float4*)g_up[1];
        const int rowi = tid >> 5, ki = lane * 4;
        float4 va = a0[tid], vb = a1[tid];
        *(float4*)(&sws[0][0][0] + rowi * PD + ki) =
            make_float4(va.x + vb.x, va.y + vb.y, va.z + vb.z, va.w + vb.w);
        va = b0[tid]; vb = b1_[tid];
        *(float4*)(&swd[0][0][0] + rowi * PD + ki) =
            make_float4(va.x + vb.x, va.y + vb.y, va.z + vb.z, va.w + vb.w);
        va = c0[tid]; vb = c1[tid];
        *(float4*)(&su[0][0][0] + rowi * PD + ki) =
            make_float4(va.x + vb.x, va.y + vb.y, va.z + vb.z, va.w + vb.w);
    }
    __syncthreads();

    // One-pass group compute: 8-lane groups; 16 groups per branch cover all jobs.
    // Jobs 0..n-1: source slots; job n: center src dot; job n+1: adst (swd).
    // Shuffles use the GROUP's 8-lane mask (trip counts differ between groups).
    {
        const int br  = warp >> 2;
        const int gl  = (warp & 3) * 4 + (lane >> 3);   // 0..15 within branch
        const int sub = lane & 7;
        const int d0  = sub * 16;
        const int n   = s_n[br];
        const unsigned gmask = 0xFFu << ((lane >> 3) * 8);

        for (int j = gl; j < n + 2; j += 16) {
            const bool isAdst   = (j == n + 1);
            const bool isCenter = (j >= n);
            const float* A = isAdst ? &swd[br][0][0] : &sws[br][0][0];
            const float* P = &su[br][0][0];
            float a0 = 0, a1 = 0, a2 = 0, a3 = 0, p0 = 0, p1 = 0, p2 = 0, p3 = 0;

            if (isCenter || j < XCAP) {
                const float* x = &s_x[br][isCenter ? XCAP : j][0];
                #pragma unroll
                for (int q = 0; q < 16; ++q) {
                    float xv = x[d0 + q];
                    a0 += xv * A[0 * PD + d0 + q]; a1 += xv * A[1 * PD + d0 + q];
                    a2 += xv * A[2 * PD + d0 + q]; a3 += xv * A[3 * PD + d0 + q];
                    p0 += xv * P[0 * PD + d0 + q]; p1 += xv * P[1 * PD + d0 + q];
                    p2 += xv * P[2 * PD + d0 + q]; p3 += xv * P[3 * PD + d0 + q];
                }
            } else {   // rare: slot beyond prefetch capacity
                const float* xg = emb + (long)s_nbr[br][s_list[br][j] & 255] * DD + d0;
                #pragma unroll
                for (int q = 0; q < 16; ++q) {
                    float xv = xg[q];
                    a0 += xv * A[0 * PD + d0 + q]; a1 += xv * A[1 * PD + d0 + q];
                    a2 += xv * A[2 * PD + d0 + q]; a3 += xv * A[3 * PD + d0 + q];
                    p0 += xv * P[0 * PD + d0 + q]; p1 += xv * P[1 * PD + d0 + q];
                    p2 += xv * P[2 * PD + d0 + q]; p3 += xv * P[3 * PD + d0 + q];
                }
            }
            #pragma unroll
            for (int o = 1; o <= 4; o <<= 1) {
                a0 += __shfl_xor_sync(gmask, a0, o);
                a1 += __shfl_xor_sync(gmask, a1, o);
                a2 += __shfl_xor_sync(gmask, a2, o);
                a3 += __shfl_xor_sync(gmask, a3, o);
                p0 += __shfl_xor_sync(gmask, p0, o);
                p1 += __shfl_xor_sync(gmask, p1, o);
                p2 += __shfl_xor_sync(gmask, p2, o);
                p3 += __shfl_xor_sync(gmask, p3, o);
            }
            if (sub == 0) {
                if (isAdst) {
                    s_adst[br][0] = a0; s_adst[br][1] = a1;
                    s_adst[br][2] = a2; s_adst[br][3] = a3;
                } else {
                    const int idx = isCenter ? LCAP : j;
                    s_e[br][idx][0] = a0; s_e[br][idx][1] = a1;
                    s_e[br][idx][2] = a2; s_e[br][idx][3] = a3;
                    s_p[br][idx][0] = p0; s_p[br][idx][1] = p1;
                    s_p[br][idx][2] = p2; s_p[br][idx][3] = p3;
                }
            }
        }
    }
    __syncthreads();

    // Final: 8 lanes, one (branch, head) each; sorted order -> deterministic
    if (warp == 0) {
        float val = 0.f;
        if (lane < 8) {
            const int brx = lane >> 2, h = lane & 3;
            const int n = s_n[brx];
            const float ad = s_adst[brx][h];
            float M = NEGINF;
            for (int i = 0; i <= n; ++i) {
                int row = (s_sorted[brx][i] >> 8) & 127;
                float e = s_e[brx][row][h] + ad;
                e = e > 0.f ? e : NEG_SLOPE * e;
                M = fmaxf(M, e);
            }
            float S = 0.f, T = 0.f;
            for (int i = 0; i <= n; ++i) {
                int row = (s_sorted[brx][i] >> 8) & 127;
                float e = s_e[brx][row][h] + ad;
                e = e > 0.f ? e : NEG_SLOPE * e;
                float w = __expf(e - M);
                S += w;
                T += w * s_p[brx][row][h];
            }
            val = __fdividef(T, S) * (1.f / HH);
        }
        #pragma unroll
        for (int o = 4; o; o >>= 1) val += __shfl_xor_sync(0xffffffffu, val, o);
        if (lane == 0) out[b] = val + g_const;
    }
}

extern "C" void kernel_launch(void* const* d_in, const int* in_sizes, int n_in,
                              void* d_out, int out_size) {
    const int*   nbr1 = (const int*)  d_in[0];
    const int*   nbr2 = (const int*)  d_in[1];
    const int*   adj1 = (const int*)  d_in[2];
    const int*   adj2 = (const int*)  d_in[3];
    const float* emb  = (const float*)d_in[4];
    const float* W1   = (const float*)d_in[5];
    const float* as1  = (const float*)d_in[6];
    const float* ad1  = (const float*)d_in[7];
    const float* b1   = (const float*)d_in[8];
    const float* W2   = (const float*)d_in[9];
    const float* as2  = (const float*)d_in[10];
    const float* ad2  = (const float*)d_in[11];
    const float* b2   = (const float*)d_in[12];
    const float* mw   = (const float*)d_in[13];
    const float* mb   = (const float*)d_in[14];
    float* out = (float*)d_out;

    gat_fused<<<NPROD + BB, 256>>>(W1, as1, ad1, W2, as2, ad2, mw, mb, b1, b2,
                                   adj1, adj2, nbr1, nbr2, emb, out);
}

// round 13
// speedup vs baseline: 1.1805x; 1.0877x over previous
#include <cuda_runtime.h>

#define BB 64
#define NN 256
#define EE 2048
#define DD 128
#define PD 132          // padded smem pitch (floats)
#define HH 4
#define LCAP 64
#define XCAP 32
#define NPROD 16
#define NEG_SLOPE 0.2f

// Folded weight partials (16 producer blocks; consumers sum the two halves)
__device__ float g_wsp[2][2 * HH * DD];
__device__ float g_wdp[2][2 * HH * DD];
__device__ float g_up [2][2 * HH * DD];
__device__ float g_const;
__device__ int   g_done = 0;   // producers arrived (0..16)
__device__ int   g_pass = 0;   // consumer blocks past the wait (0..64); last resets

__global__ __launch_bounds__(256)
void gat_fused(const float* __restrict__ W1, const float* __restrict__ as1,
               const float* __restrict__ ad1,
               const float* __restrict__ W2, const float* __restrict__ as2,
               const float* __restrict__ ad2,
               const float* __restrict__ mlp_w, const float* __restrict__ mlp_b,
               const float* __restrict__ b1, const float* __restrict__ b2,
               const int* __restrict__ adj1, const int* __restrict__ adj2,
               const int* __restrict__ nbr1, const int* __restrict__ nbr2,
               const float* __restrict__ emb, float* __restrict__ out) {
    const int tid = threadIdx.x;

    // ───────── Producer blocks: fold weights (16 blocks) ─────────
    if (blockIdx.x < NPROD) {
        __shared__ float r0[128], r1[128], r2[128];
        const int bx = blockIdx.x;
        const int br = bx >> 3, h = (bx >> 1) & 3, half = bx & 1;
        const float* W   = br ? W2  : W1;
        const float* as_ = br ? as2 : as1;
        const float* ad_ = br ? ad2 : ad1;
        const float* mw  = mlp_w + br * DD;
        const int k = tid & 127, p = tid >> 7;

        float aws = 0.f, awd = 0.f, au = 0.f;
        #pragma unroll
        for (int dd = 0; dd < 32; ++dd) {
            int d = half * 64 + p * 32 + dd;
            float wv = W[(h * DD + d) * DD + k];
            aws += wv * as_[h * DD + d];
            awd += wv * ad_[h * DD + d];
            au  += wv * mw[d];
        }
        if (p == 1) { r0[k] = aws; r1[k] = awd; r2[k] = au; }
        __syncthreads();
        if (p == 0) {
            const int idx = (br * HH + h) * DD + k;
            g_wsp[half][idx] = aws + r0[k];
            g_wdp[half][idx] = awd + r1[k];
            g_up [half][idx] = au  + r2[k];
        }
        if (bx == 0 && tid >= 128 && tid < 160) {
            int l = tid - 128;
            float c = 0.f;
            for (int d = l; d < DD; d += 32)
                c += mlp_w[d] * b1[d] + mlp_w[DD + d] * b2[d];
            #pragma unroll
            for (int o = 16; o; o >>= 1) c += __shfl_xor_sync(0xffffffffu, c, o);
            if (l == 0) g_const = c + mlp_b[0];
        }
        __syncthreads();
        if (tid == 0) { __threadfence(); atomicAdd(&g_done, 1); }
        return;
    }

    // ───────── Consumer blocks: one batch each ─────────
    __shared__ float sws[2][HH][PD], swd[2][HH][PD], su[2][HH][PD];
    __shared__ float s_x[2][XCAP + 1][PD];   // row XCAP = center node
    __shared__ int   s_nbr[2][NN];
    __shared__ int   s_list[2][LCAP];        // arrival order: e<<15 | slot<<8 | src
    __shared__ int   s_sorted[2][LCAP + 1];  // edge order + self-loop last
    __shared__ int   s_cnt[2], s_n[2];
    __shared__ float s_e[2][LCAP + 1][HH];   // raw src dots per slot (LCAP = center)
    __shared__ float s_p[2][LCAP + 1][HH];
    __shared__ float s_adst[2][HH];

    const int b = blockIdx.x - NPROD;
    const int warp = tid >> 5, lane = tid & 31;
    const float NEGINF = __int_as_float(0xff800000);

    if (tid < 2) s_cnt[tid] = 0;
    __syncthreads();

    // Stage nbr rows (independent — overlaps scan loads)
    s_nbr[0][tid] = nbr1[b * NN + tid];
    s_nbr[1][tid] = nbr2[b * NN + tid];

    // Parallel scan: 128 threads per branch, 16 edges each
    {
        const int brx = tid >> 7, t = tid & 127;
        const int e0 = t * 16;
        const int* base = (brx ? adj2 : adj1) + (long)b * 2 * EE;
        int4 vd[4], vs[4];
        #pragma unroll
        for (int q = 0; q < 4; ++q) {
            vd[q] = *(const int4*)(base + EE + e0 + 4 * q);
            vs[q] = *(const int4*)(base +      e0 + 4 * q);
        }
        #pragma unroll
        for (int q = 0; q < 4; ++q) {
            int d4[4] = { vd[q].x, vd[q].y, vd[q].z, vd[q].w };
            int s4[4] = { vs[q].x, vs[q].y, vs[q].z, vs[q].w };
            #pragma unroll
            for (int i = 0; i < 4; ++i) {
                if (d4[i] == 0) {
                    int slot = atomicAdd(&s_cnt[brx], 1);
                    if (slot < LCAP)
                        s_list[brx][slot] = ((e0 + 4 * q + i) << 15) | (slot << 8) | s4[i];
                }
            }
        }
    }
    __syncthreads();

    // Warps 1-7: gather emb rows (slot order, one float4 per lane per row).
    // Warp 0: sort into s_sorted (lanes 0/16); lane 0 polls for producers.
    if (warp > 0) {
        const int c0 = min(min(s_cnt[0], LCAP), XCAP) + 1;   // +1 = center row
        const int c1 = min(min(s_cnt[1], LCAP), XCAP) + 1;
        for (int i = warp - 1; i < c0 + c1; i += 7) {
            const int brx = (i >= c0) ? 1 : 0;
            const int li  = brx ? (i - c0) : i;
            const int cc  = brx ? c1 : c0;
            int row, src;
            if (li == cc - 1) { row = XCAP; src = 0; }
            else             { row = li;   src = s_list[brx][li] & 255; }
            const float4 v = *(const float4*)(emb + (long)s_nbr[brx][src] * DD + lane * 4);
            *(float4*)&s_x[brx][row][lane * 4] = v;
        }
    } else {
        if (lane == 0 || lane == 16) {
            const int brx = lane >> 4;
            const int n = min(s_cnt[brx], LCAP);
            for (int i = 0; i < n; ++i) {
                int key = s_list[brx][i], j = i - 1;
                while (j >= 0 && s_sorted[brx][j] > key) { s_sorted[brx][j + 1] = s_sorted[brx][j]; --j; }
                s_sorted[brx][j + 1] = key;
            }
            s_sorted[brx][n] = (EE << 15) | (LCAP << 8);   // self-loop -> center slot
            s_n[brx] = n;
        }
        if (lane == 0) {
            const volatile int* pd = &g_done;
            while (*pd < NPROD) {}
            __threadfence();
            int fin = atomicAdd(&g_pass, 1);
            if (fin == BB - 1) { g_done = 0; g_pass = 0; __threadfence(); }
        }
    }
    __syncthreads();   // weights ready + gathers + sort all complete

    // Stage folded weights block-wide: one float4 per thread per array (one L2 round)
    {
        const float4* a0 = (const float4*)g_wsp[0];
        const float4* a1 = (const float4*)g_wsp[1];
        const float4* b0 = (const float4*)g_wdp[0];
        const float4* b1_ = (const float4*)g_wdp[1];
        const float4* c0 = (const float4*)g_up[0];
        const float4* c1 = (const float4*)g_up[1];
        const int rowi = tid >> 5, ki = lane * 4;
        float4 va = a0[tid], vb = a1[tid];
        *(float4*)(&sws[0][0][0] + rowi * PD + ki) =
            make_float4(va.x + vb.x, va.y + vb.y, va.z + vb.z, va.w + vb.w);
        va = b0[tid]; vb = b1_[tid];
        *(float4*)(&swd[0][0][0] + rowi * PD + ki) =
            make_float4(va.x + vb.x, va.y + vb.y, va.z + vb.z, va.w + vb.w);
        va = c0[tid]; vb = c1[tid];
        *(float4*)(&su[0][0][0] + rowi * PD + ki) =
            make_float4(va.x + vb.x, va.y + vb.y, va.z + vb.z, va.w + vb.w);
    }
    __syncthreads();

    // One-pass group compute: 8-lane groups; 16 groups per branch cover all jobs.
    // Jobs 0..n-1: source slots; job n: center src dot; job n+1: adst (swd).
    // Shuffles use the GROUP's 8-lane mask (trip counts differ between groups).
    {
        const int br  = warp >> 2;
        const int gl  = (warp & 3) * 4 + (lane >> 3);   // 0..15 within branch
        const int sub = lane & 7;
        const int d0  = sub * 16;
        const int n   = s_n[br];
        const unsigned gmask = 0xFFu << ((lane >> 3) * 8);

        for (int j = gl; j < n + 2; j += 16) {
            const bool isAdst   = (j == n + 1);
            const bool isCenter = (j >= n);
            const float* A = isAdst ? &swd[br][0][0] : &sws[br][0][0];
            const float* P = &su[br][0][0];
            float a0 = 0, a1 = 0, a2 = 0, a3 = 0, p0 = 0, p1 = 0, p2 = 0, p3 = 0;

            if (isCenter || j < XCAP) {
                const float* x = &s_x[br][isCenter ? XCAP : j][0];
                #pragma unroll
                for (int q = 0; q < 16; ++q) {
                    float xv = x[d0 + q];
                    a0 += xv * A[0 * PD + d0 + q]; a1 += xv * A[1 * PD + d0 + q];
                    a2 += xv * A[2 * PD + d0 + q]; a3 += xv * A[3 * PD + d0 + q];
                    p0 += xv * P[0 * PD + d0 + q]; p1 += xv * P[1 * PD + d0 + q];
                    p2 += xv * P[2 * PD + d0 + q]; p3 += xv * P[3 * PD + d0 + q];
                }
            } else {   // rare: slot beyond prefetch capacity
                const float* xg = emb + (long)s_nbr[br][s_list[br][j] & 255] * DD + d0;
                #pragma unroll
                for (int q = 0; q < 16; ++q) {
                    float xv = xg[q];
                    a0 += xv * A[0 * PD + d0 + q]; a1 += xv * A[1 * PD + d0 + q];
                    a2 += xv * A[2 * PD + d0 + q]; a3 += xv * A[3 * PD + d0 + q];
                    p0 += xv * P[0 * PD + d0 + q]; p1 += xv * P[1 * PD + d0 + q];
                    p2 += xv * P[2 * PD + d0 + q]; p3 += xv * P[3 * PD + d0 + q];
                }
            }
            #pragma unroll
            for (int o = 1; o <= 4; o <<= 1) {
                a0 += __shfl_xor_sync(gmask, a0, o);
                a1 += __shfl_xor_sync(gmask, a1, o);
                a2 += __shfl_xor_sync(gmask, a2, o);
                a3 += __shfl_xor_sync(gmask, a3, o);
                p0 += __shfl_xor_sync(gmask, p0, o);
                p1 += __shfl_xor_sync(gmask, p1, o);
                p2 += __shfl_xor_sync(gmask, p2, o);
                p3 += __shfl_xor_sync(gmask, p3, o);
            }
            if (sub == 0) {
                if (isAdst) {
                    s_adst[br][0] = a0; s_adst[br][1] = a1;
                    s_adst[br][2] = a2; s_adst[br][3] = a3;
                } else {
                    const int idx = isCenter ? LCAP : j;
                    s_e[br][idx][0] = a0; s_e[br][idx][1] = a1;
                    s_e[br][idx][2] = a2; s_e[br][idx][3] = a3;
                    s_p[br][idx][0] = p0; s_p[br][idx][1] = p1;
                    s_p[br][idx][2] = p2; s_p[br][idx][3] = p3;
                }
            }
        }
    }
    __syncthreads();

    // Final: 8 lanes, one (branch, head) each; sorted order -> deterministic
    if (warp == 0) {
        float val = 0.f;
        if (lane < 8) {
            const int brx = lane >> 2, h = lane & 3;
            const int n = s_n[brx];
            const float ad = s_adst[brx][h];
            float M = NEGINF;
            for (int i = 0; i <= n; ++i) {
                int row = (s_sorted[brx][i] >> 8) & 127;
                float e = s_e[brx][row][h] + ad;
                e = e > 0.f ? e : NEG_SLOPE * e;
                M = fmaxf(M, e);
            }
            float S = 0.f, T = 0.f;
            for (int i = 0; i <= n; ++i) {
                int row = (s_sorted[brx][i] >> 8) & 127;
                float e = s_e[brx][row][h] + ad;
                e = e > 0.f ? e : NEG_SLOPE * e;
                float w = __expf(e - M);
                S += w;
                T += w * s_p[brx][row][h];
            }
            val = __fdividef(T, S) * (1.f / HH);
        }
        #pragma unroll
        for (int o = 4; o; o >>= 1) val += __shfl_xor_sync(0xffffffffu, val, o);
        if (lane == 0) out[b] = val + g_const;
    }
}

extern "C" void kernel_launch(void* const* d_in, const int* in_sizes, int n_in,
                              void* d_out, int out_size) {
    const int*   nbr1 = (const int*)  d_in[0];
    const int*   nbr2 = (const int*)  d_in[1];
    const int*   adj1 = (const int*)  d_in[2];
    const int*   adj2 = (const int*)  d_in[3];
    const float* emb  = (const float*)d_in[4];
    const float* W1   = (const float*)d_in[5];
    const float* as1  = (const float*)d_in[6];
    const float* ad1  = (const float*)d_in[7];
    const float* b1   = (const float*)d_in[8];
    const float* W2   = (const float*)d_in[9];
    const float* as2  = (const float*)d_in[10];
    const float* ad2  = (const float*)d_in[11];
    const float* b2   = (const float*)d_in[12];
    const float* mw   = (const float*)d_in[13];
    const float* mb   = (const float*)d_in[14];
    float* out = (float*)d_out;

    gat_fused<<<NPROD + BB, 256>>>(W1, as1, ad1, W2, as2, ad2, mw, mb, b1, b2,
                                   adj1, adj2, nbr1, nbr2, emb, out);
}